// round 3
// baseline (speedup 1.0000x reference)
#include <cuda_runtime.h>
#include <cstdint>

#define N_NODES   50000
#define N_EDGES   800000
#define IN_FEATS  256
#define OUT_FEATS 64

// Scratch for hw = (h @ W) * norm   [N_NODES x OUT_FEATS], 12.8 MB (L2-resident)
__device__ float g_hw[N_NODES * OUT_FEATS];
// W pre-converted to tf32 (rna) once per launch: 256*64 = 16384 elements
__device__ uint32_t g_w_tf32[IN_FEATS * OUT_FEATS];

// ---------------------------------------------------------------------------
// Kernel 0: convert W -> tf32 (rna) once. 16384 elements, vectorized.
// ---------------------------------------------------------------------------
__global__ __launch_bounds__(256)
void wconv_kernel(const float* __restrict__ W) {
    int gid = blockIdx.x * blockDim.x + threadIdx.x;   // 4096 float4s
    if (gid < IN_FEATS * OUT_FEATS / 4) {
        float4 v = *reinterpret_cast<const float4*>(W + gid * 4);
        uint4 u;
        asm("cvt.rna.tf32.f32 %0, %1;" : "=r"(u.x) : "f"(v.x));
        asm("cvt.rna.tf32.f32 %0, %1;" : "=r"(u.y) : "f"(v.y));
        asm("cvt.rna.tf32.f32 %0, %1;" : "=r"(u.z) : "f"(v.z));
        asm("cvt.rna.tf32.f32 %0, %1;" : "=r"(u.w) : "f"(v.w));
        *reinterpret_cast<uint4*>(g_w_tf32 + gid * 4) = u;
    }
}

// ---------------------------------------------------------------------------
// Kernel 1: zero d_out (it is poisoned to 0xAA before timing)
// ---------------------------------------------------------------------------
__global__ void zero_kernel(float4* __restrict__ out) {
    int gid = blockIdx.x * blockDim.x + threadIdx.x;   // 800000 float4s
    if (gid < N_NODES * OUT_FEATS / 4)
        out[gid] = make_float4(0.f, 0.f, 0.f, 0.f);
}

// ---------------------------------------------------------------------------
// Kernel 2: hw = (h @ W) * norm   via tf32 mma.sync (m16n8k8)
// A operand: RAW fp32 bits (HW truncates to tf32) -> zero per-element cvt.
// B operand: pre-converted g_w_tf32 (rna).
// Block: 128 threads = 4 warps. Tile: 64 rows x 64 cols, K chunked by 64.
// ---------------------------------------------------------------------------
#define PAD_A 68
#define PAD_B 72

__global__ __launch_bounds__(128)
void gemm_tf32_kernel(const float* __restrict__ h,
                      const float* __restrict__ norm) {
    __shared__ uint32_t shA[64 * PAD_A];
    __shared__ uint32_t shB[64 * PAD_B];

    const int tid  = threadIdx.x;
    const int warp = tid >> 5;
    const int lane = tid & 31;
    const int g    = lane >> 2;   // 0..7
    const int tg   = lane & 3;    // 0..3
    const int rowBase = blockIdx.x * 64;

    float acc[8][4];
    #pragma unroll
    for (int t = 0; t < 8; t++)
        #pragma unroll
        for (int i = 0; i < 4; i++) acc[t][i] = 0.f;

    for (int kk = 0; kk < IN_FEATS; kk += 64) {
        // Stage A chunk: raw fp32 bits, straight copy (no cvt)
        #pragma unroll
        for (int i = tid; i < 1024; i += 128) {
            int r  = i >> 4;      // 0..63
            int k4 = i & 15;      // float4 index
            int row = rowBase + r;
            uint4 u = make_uint4(0u, 0u, 0u, 0u);
            if (row < N_NODES)
                u = *reinterpret_cast<const uint4*>(h + (size_t)row * IN_FEATS + kk + k4 * 4);
            *reinterpret_cast<uint4*>(&shA[r * PAD_A + k4 * 4]) = u;
        }
        // Stage B chunk: pre-converted tf32 bits, straight copy
        #pragma unroll
        for (int i = tid; i < 1024; i += 128) {
            int r  = i >> 4;      // k row 0..63
            int k4 = i & 15;      // col float4 index
            uint4 u = *reinterpret_cast<const uint4*>(g_w_tf32 + (size_t)(kk + r) * OUT_FEATS + k4 * 4);
            *reinterpret_cast<uint4*>(&shB[r * PAD_B + k4 * 4]) = u;
        }
        __syncthreads();

        const int ar = warp * 16;
        #pragma unroll
        for (int k8 = 0; k8 < 64; k8 += 8) {
            uint32_t a0 = shA[(ar + g    ) * PAD_A + k8 + tg    ];
            uint32_t a1 = shA[(ar + g + 8) * PAD_A + k8 + tg    ];
            uint32_t a2 = shA[(ar + g    ) * PAD_A + k8 + tg + 4];
            uint32_t a3 = shA[(ar + g + 8) * PAD_A + k8 + tg + 4];
            #pragma unroll
            for (int t = 0; t < 8; t++) {
                uint32_t b0 = shB[(k8 + tg    ) * PAD_B + t * 8 + g];
                uint32_t b1 = shB[(k8 + tg + 4) * PAD_B + t * 8 + g];
                asm volatile(
                    "mma.sync.aligned.m16n8k8.row.col.f32.tf32.tf32.f32 "
                    "{%0,%1,%2,%3}, {%4,%5,%6,%7}, {%8,%9}, {%0,%1,%2,%3};"
                    : "+f"(acc[t][0]), "+f"(acc[t][1]), "+f"(acc[t][2]), "+f"(acc[t][3])
                    : "r"(a0), "r"(a1), "r"(a2), "r"(a3), "r"(b0), "r"(b1));
            }
        }
        __syncthreads();
    }

    // Store with pre-aggregation norm scale.
    int r0 = rowBase + warp * 16 + g;
    int r1 = r0 + 8;
    if (r0 < N_NODES) {
        float nv = norm[r0];
        #pragma unroll
        for (int t = 0; t < 8; t++) {
            float2 o = make_float2(acc[t][0] * nv, acc[t][1] * nv);
            *reinterpret_cast<float2*>(g_hw + (size_t)r0 * OUT_FEATS + t * 8 + tg * 2) = o;
        }
    }
    if (r1 < N_NODES) {
        float nv = norm[r1];
        #pragma unroll
        for (int t = 0; t < 8; t++) {
            float2 o = make_float2(acc[t][2] * nv, acc[t][3] * nv);
            *reinterpret_cast<float2*>(g_hw + (size_t)r1 * OUT_FEATS + t * 8 + tg * 2) = o;
        }
    }
}

// ---------------------------------------------------------------------------
// Kernel 3: scatter-add.  16 threads per edge, each handles one float4.
// Vector reduction (no return) to L2-resident destination.
// ---------------------------------------------------------------------------
__global__ __launch_bounds__(256)
void scatter_kernel(const int* __restrict__ src,
                    const int* __restrict__ dst,
                    float* __restrict__ out) {
    int gid = blockIdx.x * blockDim.x + threadIdx.x;  // 12.8M threads exactly
    int e = gid >> 4;
    int c = gid & 15;
    if (e < N_EDGES) {
        int s = __ldg(src + e);
        int d = __ldg(dst + e);
        float4 v = *reinterpret_cast<const float4*>(g_hw + (size_t)s * OUT_FEATS + c * 4);
        float* p = out + (size_t)d * OUT_FEATS + c * 4;
        asm volatile("red.global.add.v4.f32 [%0], {%1, %2, %3, %4};"
                     :: "l"(p), "f"(v.x), "f"(v.y), "f"(v.z), "f"(v.w)
                     : "memory");
    }
}

// ---------------------------------------------------------------------------
// Kernel 4: out = relu(out * norm + bias)
// ---------------------------------------------------------------------------
__global__ __launch_bounds__(256)
void epilogue_kernel(const float* __restrict__ norm,
                     const float* __restrict__ bias,
                     float* __restrict__ out) {
    int gid = blockIdx.x * blockDim.x + threadIdx.x;  // 800000 float4s
    if (gid >= N_NODES * OUT_FEATS / 4) return;
    int v = gid >> 4;
    int c = gid & 15;
    float4 o = *reinterpret_cast<float4*>(out + (size_t)gid * 4);
    float nv = norm[v];
    float4 b = *reinterpret_cast<const float4*>(bias + c * 4);
    o.x = fmaxf(fmaf(o.x, nv, b.x), 0.f);
    o.y = fmaxf(fmaf(o.y, nv, b.y), 0.f);
    o.z = fmaxf(fmaf(o.z, nv, b.z), 0.f);
    o.w = fmaxf(fmaf(o.w, nv, b.w), 0.f);
    *reinterpret_cast<float4*>(out + (size_t)gid * 4) = o;
}

// ---------------------------------------------------------------------------
// Launch
// ---------------------------------------------------------------------------
extern "C" void kernel_launch(void* const* d_in, const int* in_sizes, int n_in,
                              void* d_out, int out_size) {
    const float* h      = (const float*)d_in[0];   // [50000, 256]
    const float* norm   = (const float*)d_in[1];   // [50000, 1]
    const float* weight = (const float*)d_in[2];   // [256, 64]
    const float* bias   = (const float*)d_in[3];   // [64]
    const int*   src    = (const int*)d_in[4];     // [800000]
    const int*   dst    = (const int*)d_in[5];     // [800000]
    float* out = (float*)d_out;                    // [50000, 64]

    // 0) W -> tf32 (rna), once
    wconv_kernel<<<(IN_FEATS * OUT_FEATS / 4 + 255) / 256, 256>>>(weight);

    // 1) zero the aggregation buffer (d_out is poisoned)
    zero_kernel<<<(N_NODES * OUT_FEATS / 4 + 255) / 256, 256>>>((float4*)out);

    // 2) hw = (h @ W) * norm   (tf32 tensor cores, raw-bit A)
    gemm_tf32_kernel<<<(N_NODES + 63) / 64, 128>>>(h, norm);

    // 3) out[v] += hw[src[e]] for each edge (v = dst[e])
    int scatter_threads = N_EDGES * 16;
    scatter_kernel<<<(scatter_threads + 255) / 256, 256>>>(src, dst, out);

    // 4) out = relu(out * norm + bias)
    epilogue_kernel<<<(N_NODES * OUT_FEATS / 4 + 255) / 256, 256>>>(norm, bias, out);
}